// round 2
// baseline (speedup 1.0000x reference)
#include <cuda_runtime.h>
#include <cuda_bf16.h>
#include <cstdint>

// ---------------------------------------------------------------------------
// Problem constants
// ---------------------------------------------------------------------------
#define BATCH   16384
#define FDIM    1024
#define N_ITER  10
#define EPS_CG  1e-8f
#define RIDGE   0.001f

// ---------------------------------------------------------------------------
// Device scratch (no cudaMalloc allowed; kernels reference these directly so
// kernel_launch contains ONLY kernel launches)
// ---------------------------------------------------------------------------
__device__ float g_A [FDIM * FDIM];            // 4 MB
__device__ float g_r [(size_t)BATCH * FDIM];   // 64 MB
__device__ float g_p [(size_t)BATCH * FDIM];   // 64 MB
__device__ float g_Ap[(size_t)BATCH * FDIM];   // 64 MB
__device__ float g_rs[BATCH];

// ---------------------------------------------------------------------------
// Block reduction: returns full sum to ALL threads of a 256-thread block.
// ---------------------------------------------------------------------------
__device__ __forceinline__ float block_reduce_sum_256(float v, float* sh8) {
    int lane = threadIdx.x & 31;
    int warp = threadIdx.x >> 5;
    #pragma unroll
    for (int o = 16; o > 0; o >>= 1)
        v += __shfl_xor_sync(0xffffffffu, v, o);
    if (lane == 0) sh8[warp] = v;
    __syncthreads();
    float s = sh8[0] + sh8[1] + sh8[2] + sh8[3]
            + sh8[4] + sh8[5] + sh8[6] + sh8[7];
    __syncthreads();   // allow sh8 reuse
    return s;
}

// ---------------------------------------------------------------------------
// g_A = W^T * W + RIDGE * I      (W: [FDIM, FDIM] row-major)
// 128x128 tile, BK=8, 256 threads, 8x8 per-thread microtile.
// Both operand tiles are 8x128 row-major chunks of W (no transposed loads).
// Tiny (2.1 GFLOP) -- simplicity over speed here.
// ---------------------------------------------------------------------------
__global__ __launch_bounds__(256) void gemm_ata(const float* __restrict__ W) {
    __shared__ float As[8][128];   // As[k][m] = W[k0+k][bm+m]
    __shared__ float Bs[8][128];   // Bs[k][n] = W[k0+k][bn+n]

    const int bm  = blockIdx.y * 128;
    const int bn  = blockIdx.x * 128;
    const int tid = threadIdx.x;
    const int tx  = tid & 15;      // 0..15 -> column group
    const int ty  = tid >> 4;      // 0..15 -> row group

    const int lrow = tid >> 5;          // 0..7
    const int lcol = (tid & 31) * 4;    // 0..124

    float acc[8][8];
    #pragma unroll
    for (int i = 0; i < 8; i++)
        #pragma unroll
        for (int j = 0; j < 8; j++) acc[i][j] = 0.f;

    for (int k0 = 0; k0 < FDIM; k0 += 8) {
        const float* wrow = W + (size_t)(k0 + lrow) * FDIM;
        *(float4*)&As[lrow][lcol] = *(const float4*)(wrow + bm + lcol);
        *(float4*)&Bs[lrow][lcol] = *(const float4*)(wrow + bn + lcol);
        __syncthreads();

        #pragma unroll
        for (int k = 0; k < 8; k++) {
            float a[8], b[8];
            #pragma unroll
            for (int i = 0; i < 8; i++) a[i] = As[k][ty * 8 + i];
            #pragma unroll
            for (int j = 0; j < 8; j++) b[j] = Bs[k][tx * 8 + j];
            #pragma unroll
            for (int i = 0; i < 8; i++)
                #pragma unroll
                for (int j = 0; j < 8; j++)
                    acc[i][j] = fmaf(a[i], b[j], acc[i][j]);
        }
        __syncthreads();
    }

    #pragma unroll
    for (int i = 0; i < 8; i++) {
        int row = bm + ty * 8 + i;
        float* out = g_A + (size_t)row * FDIM + bn + tx * 8;
        #pragma unroll
        for (int j = 0; j < 8; j++) {
            float v = acc[i][j];
            if (row == bn + tx * 8 + j) v += RIDGE;
            out[j] = v;
        }
    }
}

// ---------------------------------------------------------------------------
// g_Ap = g_p * g_A    (p: [BATCH, FDIM], A: [FDIM, FDIM] row-major, A == A^T)
// 128x128 tile, BK=16, 256 threads, 8x8 microtile, double-buffered smem,
// LDG-prefetch into registers before compute. One __syncthreads per K-tile.
// ---------------------------------------------------------------------------
__global__ __launch_bounds__(256) void sgemm128(void) {
    __shared__ float As[2][16][128];   // As[buf][k][m] = p[bm+m][k0+k]
    __shared__ float Bs[2][16][128];   // Bs[buf][k][n] = A[k0+k][bn+n]

    const int bm  = blockIdx.y * 128;
    const int bn  = blockIdx.x * 128;
    const int tid = threadIdx.x;
    const int tx  = tid & 15;
    const int ty  = tid >> 4;

    // p tile loader: 128 rows x 16 cols, 2 float4 per thread (rows pr, pr+64)
    const int pr = tid >> 2;            // 0..63
    const int pc = (tid & 3) * 4;       // 0,4,8,12
    // A tile loader: 16 rows x 128 cols, 2 float4 per thread (rows ar, ar+8)
    const int ar = tid >> 5;            // 0..7
    const int ac = (tid & 31) * 4;      // 0..124

    const float* prow0 = g_p + (size_t)(bm + pr)      * FDIM;
    const float* prow1 = g_p + (size_t)(bm + pr + 64) * FDIM;

    float acc[8][8];
    #pragma unroll
    for (int i = 0; i < 8; i++)
        #pragma unroll
        for (int j = 0; j < 8; j++) acc[i][j] = 0.f;

    // ---- preload tile 0 into buffer 0 ----
    {
        float4 pv0 = *(const float4*)(prow0 + pc);
        float4 pv1 = *(const float4*)(prow1 + pc);
        float4 av0 = *(const float4*)(g_A + (size_t)(ar)     * FDIM + bn + ac);
        float4 av1 = *(const float4*)(g_A + (size_t)(ar + 8) * FDIM + bn + ac);
        As[0][pc + 0][pr]      = pv0.x; As[0][pc + 1][pr]      = pv0.y;
        As[0][pc + 2][pr]      = pv0.z; As[0][pc + 3][pr]      = pv0.w;
        As[0][pc + 0][pr + 64] = pv1.x; As[0][pc + 1][pr + 64] = pv1.y;
        As[0][pc + 2][pr + 64] = pv1.z; As[0][pc + 3][pr + 64] = pv1.w;
        *(float4*)&Bs[0][ar][ac]     = av0;
        *(float4*)&Bs[0][ar + 8][ac] = av1;
    }
    __syncthreads();

    for (int k0 = 0; k0 < FDIM; k0 += 16) {
        const int buf  = (k0 >> 4) & 1;
        const bool has_next = (k0 + 16) < FDIM;

        // issue next tile's global loads early (latency hidden under compute)
        float4 pv0, pv1, av0, av1;
        if (has_next) {
            const int kn = k0 + 16;
            pv0 = *(const float4*)(prow0 + kn + pc);
            pv1 = *(const float4*)(prow1 + kn + pc);
            av0 = *(const float4*)(g_A + (size_t)(kn + ar)     * FDIM + bn + ac);
            av1 = *(const float4*)(g_A + (size_t)(kn + ar + 8) * FDIM + bn + ac);
        }

        #pragma unroll
        for (int k = 0; k < 16; k++) {
            float a[8], b[8];
            #pragma unroll
            for (int i = 0; i < 8; i++) a[i] = As[buf][k][ty * 8 + i];
            #pragma unroll
            for (int j = 0; j < 8; j++) b[j] = Bs[buf][k][tx * 8 + j];
            #pragma unroll
            for (int i = 0; i < 8; i++)
                #pragma unroll
                for (int j = 0; j < 8; j++)
                    acc[i][j] = fmaf(a[i], b[j], acc[i][j]);
        }

        if (has_next) {
            const int nb = buf ^ 1;
            As[nb][pc + 0][pr]      = pv0.x; As[nb][pc + 1][pr]      = pv0.y;
            As[nb][pc + 2][pr]      = pv0.z; As[nb][pc + 3][pr]      = pv0.w;
            As[nb][pc + 0][pr + 64] = pv1.x; As[nb][pc + 1][pr + 64] = pv1.y;
            As[nb][pc + 2][pr + 64] = pv1.z; As[nb][pc + 3][pr + 64] = pv1.w;
            *(float4*)&Bs[nb][ar][ac]     = av0;
            *(float4*)&Bs[nb][ar + 8][ac] = av1;
        }
        __syncthreads();
    }

    #pragma unroll
    for (int i = 0; i < 8; i++) {
        float* out = g_Ap + (size_t)(bm + ty * 8 + i) * FDIM + bn + tx * 8;
        *(float4*)(out + 0) = make_float4(acc[i][0], acc[i][1], acc[i][2], acc[i][3]);
        *(float4*)(out + 4) = make_float4(acc[i][4], acc[i][5], acc[i][6], acc[i][7]);
    }
}

// ---------------------------------------------------------------------------
// Init: x = 0, r = b, p = b, rs = ||b||^2   (one 256-thread block per row)
// ---------------------------------------------------------------------------
__global__ __launch_bounds__(256) void cg_init(const float* __restrict__ b,
                                               float* __restrict__ x) {
    __shared__ float sh8[8];
    const size_t off = (size_t)blockIdx.x * FDIM;
    const int t = threadIdx.x;

    float4 v = ((const float4*)(b + off))[t];
    ((float4*)(x   + off))[t] = make_float4(0.f, 0.f, 0.f, 0.f);
    ((float4*)(g_r + off))[t] = v;
    ((float4*)(g_p + off))[t] = v;

    float s = v.x * v.x + v.y * v.y + v.z * v.z + v.w * v.w;
    s = block_reduce_sum_256(s, sh8);
    if (t == 0) g_rs[blockIdx.x] = s;
}

// ---------------------------------------------------------------------------
// One fused CG vector step per row:
//   pAp  = p . Ap                (block reduce)
//   alpha= rs_old / (pAp + EPS)
//   x   += alpha p ; r -= alpha Ap
//   rs_n = r . r                 (block reduce)
//   beta = rs_n / (rs_old + EPS)
//   p    = r + beta p ; rs_old = rs_n
// ---------------------------------------------------------------------------
__global__ __launch_bounds__(256) void cg_update(float* __restrict__ x) {
    __shared__ float sh8[8];
    const size_t off = (size_t)blockIdx.x * FDIM;
    const int t = threadIdx.x;

    float4 pv  = ((const float4*)(g_p  + off))[t];
    float4 apv = ((const float4*)(g_Ap + off))[t];

    float d = pv.x * apv.x + pv.y * apv.y + pv.z * apv.z + pv.w * apv.w;
    float pAp = block_reduce_sum_256(d, sh8);

    const float rs_old = g_rs[blockIdx.x];
    const float alpha  = rs_old / (pAp + EPS_CG);

    float4 xv = ((const float4*)(x   + off))[t];
    float4 rv = ((const float4*)(g_r + off))[t];

    xv.x = fmaf(alpha, pv.x, xv.x);   xv.y = fmaf(alpha, pv.y, xv.y);
    xv.z = fmaf(alpha, pv.z, xv.z);   xv.w = fmaf(alpha, pv.w, xv.w);
    rv.x = fmaf(-alpha, apv.x, rv.x); rv.y = fmaf(-alpha, apv.y, rv.y);
    rv.z = fmaf(-alpha, apv.z, rv.z); rv.w = fmaf(-alpha, apv.w, rv.w);

    ((float4*)(x + off))[t] = xv;

    float rn = rv.x * rv.x + rv.y * rv.y + rv.z * rv.z + rv.w * rv.w;
    float rs_new = block_reduce_sum_256(rn, sh8);

    const float beta = rs_new / (rs_old + EPS_CG);

    pv.x = fmaf(beta, pv.x, rv.x);  pv.y = fmaf(beta, pv.y, rv.y);
    pv.z = fmaf(beta, pv.z, rv.z);  pv.w = fmaf(beta, pv.w, rv.w);

    ((float4*)(g_r + off))[t] = rv;
    ((float4*)(g_p + off))[t] = pv;
    if (t == 0) g_rs[blockIdx.x] = rs_new;
}

// ---------------------------------------------------------------------------
// kernel_launch -- kernel launches ONLY (graph-capturable, allocation-free)
//   d_in[0] = x      [16384 x 1024] f32   (the RHS b)
//   d_in[1] = weight [1024 x 1024]  f32
//   d_out   = solution [16384 x 1024] f32
// ---------------------------------------------------------------------------
extern "C" void kernel_launch(void* const* d_in, const int* in_sizes, int n_in,
                              void* d_out, int out_size) {
    (void)n_in; (void)out_size;

    // Defensive input-order detection by element count.
    const float* b;
    const float* W;
    if (in_sizes[0] == FDIM * FDIM) {         // weight came first
        W = (const float*)d_in[0];
        b = (const float*)d_in[1];
    } else {
        b = (const float*)d_in[0];
        W = (const float*)d_in[1];
    }
    float* x = (float*)d_out;

    // A = W^T W + ridge I
    gemm_ata<<<dim3(FDIM / 128, FDIM / 128), 256>>>(W);

    // x=0, r=p=b, rs=||b||^2
    cg_init<<<BATCH, 256>>>(b, x);

    for (int it = 0; it < N_ITER; ++it) {
        sgemm128<<<dim3(FDIM / 128, BATCH / 128), 256>>>();
        cg_update<<<BATCH, 256>>>(x);
    }
}

// round 5
// speedup vs baseline: 1.1531x; 1.1531x over previous
#include <cuda_runtime.h>
#include <cuda_bf16.h>
#include <cstdint>

// ---------------------------------------------------------------------------
// Problem constants
// ---------------------------------------------------------------------------
#define BATCH   16384
#define FDIM    1024
#define N_ITER  10
#define EPS_CG  1e-8f
#define RIDGE   0.001f

// Tensor-core GEMM tiling (legacy mma.sync path, valid on base sm_100)
#define TILE_M     128
#define TILE_N     128
#define KC         16                    // K per pipeline chunk
#define NCHUNK     (FDIM / KC)           // 64
#define ROW_STRIDE 20                    // 16 data floats + 4 pad (bank-conflict-free)
#define TILEFLOATS (128 * ROW_STRIDE)    // 2560 floats = 10240 B per operand tile
#define BUFFLOATS  (4 * TILEFLOATS)      // phi, plo, bhi, blo per buffer
#define SMEM_DYN   (2 * BUFFLOATS * 4)   // 81920 bytes, double buffered

// ---------------------------------------------------------------------------
// Device scratch (no cudaMalloc allowed)
// ---------------------------------------------------------------------------
__device__ float g_Ahi[FDIM * FDIM];            // 4 MB
__device__ float g_Alo[FDIM * FDIM];            // 4 MB
__device__ float g_phi[(size_t)BATCH * FDIM];   // 64 MB
__device__ float g_plo[(size_t)BATCH * FDIM];   // 64 MB
__device__ float g_r  [(size_t)BATCH * FDIM];   // 64 MB
__device__ float g_Ap [(size_t)BATCH * FDIM];   // 64 MB
__device__ float g_rs [BATCH];

// ---------------------------------------------------------------------------
// Helpers
// ---------------------------------------------------------------------------
__device__ __forceinline__ uint32_t smem_u32(const void* p) {
    uint32_t a;
    asm("{ .reg .u64 t; cvta.to.shared.u64 t, %1; cvt.u32.u64 %0, t; }"
        : "=r"(a) : "l"(p));
    return a;
}

__device__ __forceinline__ float tf32_hi(float x) {
    uint32_t b;
    asm("cvt.rna.tf32.f32 %0, %1;" : "=r"(b) : "f"(x));
    return __uint_as_float(b);
}

__device__ __forceinline__ void cp_async16(uint32_t smem_dst, const void* gsrc) {
    asm volatile("cp.async.cg.shared.global [%0], [%1], 16;"
                 :: "r"(smem_dst), "l"(gsrc) : "memory");
}

#define CP_COMMIT()      asm volatile("cp.async.commit_group;" ::: "memory")
#define CP_WAIT(n)       asm volatile("cp.async.wait_group %0;" :: "n"(n) : "memory")

// D += A * B  (m16n8k8, tf32 inputs in .b32 regs, fp32 accum)
__device__ __forceinline__ void mma_tf32(float* c, const uint32_t* a,
                                         uint32_t b0, uint32_t b1) {
    asm volatile(
        "mma.sync.aligned.m16n8k8.row.col.f32.tf32.tf32.f32 "
        "{%0,%1,%2,%3}, {%4,%5,%6,%7}, {%8,%9}, {%0,%1,%2,%3};"
        : "+f"(c[0]), "+f"(c[1]), "+f"(c[2]), "+f"(c[3])
        : "r"(a[0]), "r"(a[1]), "r"(a[2]), "r"(a[3]), "r"(b0), "r"(b1));
}

// ---------------------------------------------------------------------------
// Block reduction: returns full sum to ALL threads of a 256-thread block.
// ---------------------------------------------------------------------------
__device__ __forceinline__ float block_reduce_sum_256(float v, float* sh8) {
    int lane = threadIdx.x & 31;
    int warp = threadIdx.x >> 5;
    #pragma unroll
    for (int o = 16; o > 0; o >>= 1)
        v += __shfl_xor_sync(0xffffffffu, v, o);
    if (lane == 0) sh8[warp] = v;
    __syncthreads();
    float s = sh8[0] + sh8[1] + sh8[2] + sh8[3]
            + sh8[4] + sh8[5] + sh8[6] + sh8[7];
    __syncthreads();
    return s;
}

// ---------------------------------------------------------------------------
// g_Ahi/g_Alo = tf32 split of (W^T W + RIDGE I)      (W: [FDIM,FDIM] row-major)
// Tiny (2.1 GFLOP) FFMA kernel.
// ---------------------------------------------------------------------------
__global__ __launch_bounds__(256) void gemm_ata(const float* __restrict__ W) {
    __shared__ float As[8][128];
    __shared__ float Bs[8][128];

    const int bm  = blockIdx.y * 128;
    const int bn  = blockIdx.x * 128;
    const int tid = threadIdx.x;
    const int tx  = tid & 15;
    const int ty  = tid >> 4;
    const int lrow = tid >> 5;
    const int lcol = (tid & 31) * 4;

    float acc[8][8];
    #pragma unroll
    for (int i = 0; i < 8; i++)
        #pragma unroll
        for (int j = 0; j < 8; j++) acc[i][j] = 0.f;

    for (int k0 = 0; k0 < FDIM; k0 += 8) {
        const float* wrow = W + (size_t)(k0 + lrow) * FDIM;
        *(float4*)&As[lrow][lcol] = *(const float4*)(wrow + bm + lcol);
        *(float4*)&Bs[lrow][lcol] = *(const float4*)(wrow + bn + lcol);
        __syncthreads();
        #pragma unroll
        for (int k = 0; k < 8; k++) {
            float a[8], b[8];
            #pragma unroll
            for (int i = 0; i < 8; i++) a[i] = As[k][ty * 8 + i];
            #pragma unroll
            for (int j = 0; j < 8; j++) b[j] = Bs[k][tx * 8 + j];
            #pragma unroll
            for (int i = 0; i < 8; i++)
                #pragma unroll
                for (int j = 0; j < 8; j++)
                    acc[i][j] = fmaf(a[i], b[j], acc[i][j]);
        }
        __syncthreads();
    }

    #pragma unroll
    for (int i = 0; i < 8; i++) {
        int row = bm + ty * 8 + i;
        size_t o = (size_t)row * FDIM + bn + tx * 8;
        #pragma unroll
        for (int j = 0; j < 8; j++) {
            float v = acc[i][j];
            if (row == bn + tx * 8 + j) v += RIDGE;
            float hi = tf32_hi(v);
            g_Ahi[o + j] = hi;
            g_Alo[o + j] = v - hi;
        }
    }
}

// ---------------------------------------------------------------------------
// Tensor-core GEMM (legacy mma.sync, 3xTF32):  g_Ap = p * A
//   p split:  g_phi + g_plo  ([BATCH, FDIM])
//   A split:  g_Ahi + g_Alo  ([FDIM, FDIM], symmetric -> B-operand rows are
//             plain row-major reads of A)
// CTA: 256 thr = 8 warps (4M x 2N), tile 128x128, KC=16, cp.async double buf.
// Smem tiles [128][20] floats: fragment LDS is bank-conflict-free.
// ---------------------------------------------------------------------------
__global__ __launch_bounds__(256, 2) void sgemm_tc() {
    extern __shared__ __align__(16) float ds[];

    const int tid    = threadIdx.x;
    const int lane   = tid & 31;
    const int wid    = tid >> 5;
    const int warp_m = wid & 3;          // 0..3  -> 32-row slice
    const int warp_n = wid >> 2;         // 0..1  -> 64-col slice
    const int bm     = blockIdx.y * TILE_M;
    const int bn     = blockIdx.x * TILE_N;

    const uint32_t dsb = smem_u32(ds);

    // cp.async loader mapping: 2 slots/thread/tile; slot -> (row, 16B chunk)
    const int s0_row = (tid)        >> 1;          // slot j=0: rows 0..127
    const int s0_c   = ((tid)       & 1) * 2;      // chunk 0 or 2 (we do 2 chunks)
    // Each thread loads rows s0_row, chunks {s0_c, s0_c+1} => 2x16B = 8 floats

    const float* srcA_hi = g_phi + (size_t)(bm + s0_row) * FDIM;
    const float* srcA_lo = g_plo + (size_t)(bm + s0_row) * FDIM;
    const float* srcB_hi = g_Ahi + (size_t)(bn + s0_row) * FDIM;
    const float* srcB_lo = g_Alo + (size_t)(bn + s0_row) * FDIM;
    const uint32_t srow  = (uint32_t)s0_row * (ROW_STRIDE * 4);   // bytes

    float acc[2][8][4];
    #pragma unroll
    for (int mt = 0; mt < 2; mt++)
        #pragma unroll
        for (int nt = 0; nt < 8; nt++)
            #pragma unroll
            for (int k = 0; k < 4; k++) acc[mt][nt][k] = 0.f;

    // stage one chunk (k0) into buffer buf
    auto stage = [&](int k0, int buf) {
        const uint32_t base = dsb + (uint32_t)buf * (BUFFLOATS * 4);
        #pragma unroll
        for (int c = 0; c < 2; c++) {
            const uint32_t so = srow + (uint32_t)(s0_c + c) * 16;
            const int go = k0 + (s0_c + c) * 4;
            cp_async16(base + 0 * (TILEFLOATS * 4) + so, srcA_hi + go);
            cp_async16(base + 1 * (TILEFLOATS * 4) + so, srcA_lo + go);
            cp_async16(base + 2 * (TILEFLOATS * 4) + so, srcB_hi + go);
            cp_async16(base + 3 * (TILEFLOATS * 4) + so, srcB_lo + go);
        }
        CP_COMMIT();
    };

    stage(0, 0);

    #pragma unroll 1
    for (int i = 0; i < NCHUNK; i++) {
        const int buf = i & 1;

        __syncthreads();                    // prev compute done; buf^1 free
        if (i + 1 < NCHUNK) {
            stage((i + 1) * KC, buf ^ 1);
            CP_WAIT(1);                     // chunk i resident
        } else {
            CP_WAIT(0);
        }
        __syncthreads();                    // chunk i visible to all

        const float* sAhi = ds + (size_t)buf * BUFFLOATS + 0 * TILEFLOATS;
        const float* sAlo = ds + (size_t)buf * BUFFLOATS + 1 * TILEFLOATS;
        const float* sBhi = ds + (size_t)buf * BUFFLOATS + 2 * TILEFLOATS;
        const float* sBlo = ds + (size_t)buf * BUFFLOATS + 3 * TILEFLOATS;

        #pragma unroll
        for (int kst = 0; kst < KC / 8; kst++) {
            const int kb = kst * 8 + (lane & 3);    // frag k base
            uint32_t aH[2][4], aL[2][4];
            #pragma unroll
            for (int mt = 0; mt < 2; mt++) {
                const int r0 = warp_m * 32 + mt * 16 + (lane >> 2);
                const int i00 = r0 * ROW_STRIDE + kb;
                const int i10 = (r0 + 8) * ROW_STRIDE + kb;
                aH[mt][0] = __float_as_uint(sAhi[i00]);
                aH[mt][1] = __float_as_uint(sAhi[i10]);
                aH[mt][2] = __float_as_uint(sAhi[i00 + 4]);
                aH[mt][3] = __float_as_uint(sAhi[i10 + 4]);
                aL[mt][0] = __float_as_uint(sAlo[i00]);
                aL[mt][1] = __float_as_uint(sAlo[i10]);
                aL[mt][2] = __float_as_uint(sAlo[i00 + 4]);
                aL[mt][3] = __float_as_uint(sAlo[i10 + 4]);
            }
            #pragma unroll
            for (int nt = 0; nt < 8; nt++) {
                const int nr = warp_n * 64 + nt * 8 + (lane >> 2);
                const int ib = nr * ROW_STRIDE + kb;
                const uint32_t bH0 = __float_as_uint(sBhi[ib]);
                const uint32_t bH1 = __float_as_uint(sBhi[ib + 4]);
                const uint32_t bL0 = __float_as_uint(sBlo[ib]);
                const uint32_t bL1 = __float_as_uint(sBlo[ib + 4]);
                #pragma unroll
                for (int mt = 0; mt < 2; mt++) {
                    mma_tf32(acc[mt][nt], aH[mt], bH0, bH1);   // hi*hi
                    mma_tf32(acc[mt][nt], aH[mt], bL0, bL1);   // hi*lo
                    mma_tf32(acc[mt][nt], aL[mt], bH0, bH1);   // lo*hi
                }
            }
        }
    }

    // epilogue: c-fragment layout m16n8 -> float2 stores
    #pragma unroll
    for (int mt = 0; mt < 2; mt++) {
        const int row0 = bm + warp_m * 32 + mt * 16 + (lane >> 2);
        #pragma unroll
        for (int nt = 0; nt < 8; nt++) {
            const int col = bn + warp_n * 64 + nt * 8 + 2 * (lane & 3);
            float* o0 = g_Ap + (size_t)row0 * FDIM + col;
            float* o1 = g_Ap + (size_t)(row0 + 8) * FDIM + col;
            *(float2*)o0 = make_float2(acc[mt][nt][0], acc[mt][nt][1]);
            *(float2*)o1 = make_float2(acc[mt][nt][2], acc[mt][nt][3]);
        }
    }
}

// ---------------------------------------------------------------------------
// Init: x = 0, r = b, (phi,plo) = split(b), rs = ||b||^2
// ---------------------------------------------------------------------------
__global__ __launch_bounds__(256) void cg_init(const float* __restrict__ b,
                                               float* __restrict__ x) {
    __shared__ float sh8[8];
    const size_t off = (size_t)blockIdx.x * FDIM;
    const int t = threadIdx.x;

    float4 v = ((const float4*)(b + off))[t];
    ((float4*)(x   + off))[t] = make_float4(0.f, 0.f, 0.f, 0.f);
    ((float4*)(g_r + off))[t] = v;

    float4 hi = make_float4(tf32_hi(v.x), tf32_hi(v.y), tf32_hi(v.z), tf32_hi(v.w));
    float4 lo = make_float4(v.x - hi.x, v.y - hi.y, v.z - hi.z, v.w - hi.w);
    ((float4*)(g_phi + off))[t] = hi;
    ((float4*)(g_plo + off))[t] = lo;

    float s = v.x * v.x + v.y * v.y + v.z * v.z + v.w * v.w;
    s = block_reduce_sum_256(s, sh8);
    if (t == 0) g_rs[blockIdx.x] = s;
}

// ---------------------------------------------------------------------------
// Fused per-row CG vector step (p reconstructed exactly as phi + plo):
//   pAp; alpha; x += alpha p; r -= alpha Ap; rs_new; beta;
//   p_new = r + beta p  -> stored as split (phi, plo)
// ---------------------------------------------------------------------------
__global__ __launch_bounds__(256) void cg_update(float* __restrict__ x) {
    __shared__ float sh8[8];
    const size_t off = (size_t)blockIdx.x * FDIM;
    const int t = threadIdx.x;

    float4 ph  = ((const float4*)(g_phi + off))[t];
    float4 pl  = ((const float4*)(g_plo + off))[t];
    float4 pv  = make_float4(ph.x + pl.x, ph.y + pl.y, ph.z + pl.z, ph.w + pl.w);
    float4 apv = ((const float4*)(g_Ap + off))[t];

    float d = pv.x * apv.x + pv.y * apv.y + pv.z * apv.z + pv.w * apv.w;
    float pAp = block_reduce_sum_256(d, sh8);

    const float rs_old = g_rs[blockIdx.x];
    const float alpha  = rs_old / (pAp + EPS_CG);

    float4 xv = ((const float4*)(x   + off))[t];
    float4 rv = ((const float4*)(g_r + off))[t];

    xv.x = fmaf(alpha, pv.x, xv.x);   xv.y = fmaf(alpha, pv.y, xv.y);
    xv.z = fmaf(alpha, pv.z, xv.z);   xv.w = fmaf(alpha, pv.w, xv.w);
    rv.x = fmaf(-alpha, apv.x, rv.x); rv.y = fmaf(-alpha, apv.y, rv.y);
    rv.z = fmaf(-alpha, apv.z, rv.z); rv.w = fmaf(-alpha, apv.w, rv.w);

    ((float4*)(x + off))[t] = xv;

    float rn = rv.x * rv.x + rv.y * rv.y + rv.z * rv.z + rv.w * rv.w;
    float rs_new = block_reduce_sum_256(rn, sh8);

    const float beta = rs_new / (rs_old + EPS_CG);

    float4 pn;
    pn.x = fmaf(beta, pv.x, rv.x);  pn.y = fmaf(beta, pv.y, rv.y);
    pn.z = fmaf(beta, pv.z, rv.z);  pn.w = fmaf(beta, pv.w, rv.w);

    ((float4*)(g_r + off))[t] = rv;

    float4 hi = make_float4(tf32_hi(pn.x), tf32_hi(pn.y), tf32_hi(pn.z), tf32_hi(pn.w));
    float4 lo = make_float4(pn.x - hi.x, pn.y - hi.y, pn.z - hi.z, pn.w - hi.w);
    ((float4*)(g_phi + off))[t] = hi;
    ((float4*)(g_plo + off))[t] = lo;

    if (t == 0) g_rs[blockIdx.x] = rs_new;
}

// ---------------------------------------------------------------------------
// kernel_launch
//   d_in: b [16384x1024] f32, weight [1024x1024] f32 (order auto-detected)
//   d_out: solution [16384x1024] f32
// ---------------------------------------------------------------------------
extern "C" void kernel_launch(void* const* d_in, const int* in_sizes, int n_in,
                              void* d_out, int out_size) {
    (void)n_in; (void)out_size;

    const float* b;
    const float* W;
    if (in_sizes[0] == FDIM * FDIM) {
        W = (const float*)d_in[0];
        b = (const float*)d_in[1];
    } else {
        b = (const float*)d_in[0];
        W = (const float*)d_in[1];
    }
    float* x = (float*)d_out;

    cudaFuncSetAttribute(sgemm_tc, cudaFuncAttributeMaxDynamicSharedMemorySize,
                         SMEM_DYN);

    // A = W^T W + ridge I  (written directly as tf32 hi/lo split)
    gemm_ata<<<dim3(FDIM / 128, FDIM / 128), 256>>>(W);

    // x=0, r=b, (phi,plo)=split(b), rs=||b||^2
    cg_init<<<BATCH, 256>>>(b, x);

    for (int it = 0; it < N_ITER; ++it) {
        sgemm_tc<<<dim3(FDIM / TILE_N, BATCH / TILE_M), 256, SMEM_DYN>>>();
        cg_update<<<BATCH, 256>>>(x);
    }
}

// round 6
// speedup vs baseline: 1.2316x; 1.0681x over previous
#include <cuda_runtime.h>
#include <cuda_bf16.h>
#include <cstdint>

// ---------------------------------------------------------------------------
// Problem constants
// ---------------------------------------------------------------------------
#define BATCH   16384
#define FDIM    1024
#define N_ITER  10
#define EPS_CG  1e-8f
#define RIDGE   0.001f

// Tensor-core GEMM tiling (legacy mma.sync path, base sm_100)
#define TILE_M     128
#define TILE_N     128
#define KC         32                    // K per pipeline chunk (4 ksts of 8)
#define NCHUNK     (FDIM / KC)           // 32
#define ROW_STRIDE 36                    // 32 data floats + 4 pad (conflict-free)
#define TILEFLOATS (128 * ROW_STRIDE)    // 4608 floats = 18432 B per tile
#define BUFFLOATS  (2 * TILEFLOATS)      // A(p) tile + B(A) tile per buffer
#define SMEM_DYN   (2 * BUFFLOATS * 4)   // 73728 B, double buffered

// ---------------------------------------------------------------------------
// Device scratch (no cudaMalloc allowed) -- all plain fp32 now
// ---------------------------------------------------------------------------
__device__ float g_A [FDIM * FDIM];             // 4 MB
__device__ float g_p [(size_t)BATCH * FDIM];    // 64 MB
__device__ float g_r [(size_t)BATCH * FDIM];    // 64 MB
__device__ float g_Ap[(size_t)BATCH * FDIM];    // 64 MB
__device__ float g_rs[BATCH];

// ---------------------------------------------------------------------------
// Helpers
// ---------------------------------------------------------------------------
__device__ __forceinline__ float tf32_hi(float x) {
    uint32_t b;
    asm("cvt.rna.tf32.f32 %0, %1;" : "=r"(b) : "f"(x));
    return __uint_as_float(b);
}

__device__ __forceinline__ void cp_async16(uint32_t smem_dst, const void* gsrc) {
    asm volatile("cp.async.cg.shared.global [%0], [%1], 16;"
                 :: "r"(smem_dst), "l"(gsrc) : "memory");
}

#define CP_COMMIT()  asm volatile("cp.async.commit_group;" ::: "memory")
#define CP_WAIT(n)   asm volatile("cp.async.wait_group %0;" :: "n"(n) : "memory")

__device__ __forceinline__ uint32_t smem_u32(const void* p) {
    uint32_t a;
    asm("{ .reg .u64 t; cvta.to.shared.u64 t, %1; cvt.u32.u64 %0, t; }"
        : "=r"(a) : "l"(p));
    return a;
}

// D += A * B  (m16n8k8, tf32 inputs in .b32 regs, fp32 accum)
__device__ __forceinline__ void mma_tf32(float* c, const uint32_t* a,
                                         uint32_t b0, uint32_t b1) {
    asm volatile(
        "mma.sync.aligned.m16n8k8.row.col.f32.tf32.tf32.f32 "
        "{%0,%1,%2,%3}, {%4,%5,%6,%7}, {%8,%9}, {%0,%1,%2,%3};"
        : "+f"(c[0]), "+f"(c[1]), "+f"(c[2]), "+f"(c[3])
        : "r"(a[0]), "r"(a[1]), "r"(a[2]), "r"(a[3]), "r"(b0), "r"(b1));
}

// ---------------------------------------------------------------------------
// Block reduction: returns full sum to ALL threads of a 256-thread block.
// ---------------------------------------------------------------------------
__device__ __forceinline__ float block_reduce_sum_256(float v, float* sh8) {
    int lane = threadIdx.x & 31;
    int warp = threadIdx.x >> 5;
    #pragma unroll
    for (int o = 16; o > 0; o >>= 1)
        v += __shfl_xor_sync(0xffffffffu, v, o);
    if (lane == 0) sh8[warp] = v;
    __syncthreads();
    float s = sh8[0] + sh8[1] + sh8[2] + sh8[3]
            + sh8[4] + sh8[5] + sh8[6] + sh8[7];
    __syncthreads();
    return s;
}

// ---------------------------------------------------------------------------
// g_A = W^T W + RIDGE I      (W: [FDIM,FDIM] row-major)  -- tiny FFMA kernel
// ---------------------------------------------------------------------------
__global__ __launch_bounds__(256) void gemm_ata(const float* __restrict__ W) {
    __shared__ float As[8][128];
    __shared__ float Bs[8][128];

    const int bm  = blockIdx.y * 128;
    const int bn  = blockIdx.x * 128;
    const int tid = threadIdx.x;
    const int tx  = tid & 15;
    const int ty  = tid >> 4;
    const int lrow = tid >> 5;
    const int lcol = (tid & 31) * 4;

    float acc[8][8];
    #pragma unroll
    for (int i = 0; i < 8; i++)
        #pragma unroll
        for (int j = 0; j < 8; j++) acc[i][j] = 0.f;

    for (int k0 = 0; k0 < FDIM; k0 += 8) {
        const float* wrow = W + (size_t)(k0 + lrow) * FDIM;
        *(float4*)&As[lrow][lcol] = *(const float4*)(wrow + bm + lcol);
        *(float4*)&Bs[lrow][lcol] = *(const float4*)(wrow + bn + lcol);
        __syncthreads();
        #pragma unroll
        for (int k = 0; k < 8; k++) {
            float a[8], b[8];
            #pragma unroll
            for (int i = 0; i < 8; i++) a[i] = As[k][ty * 8 + i];
            #pragma unroll
            for (int j = 0; j < 8; j++) b[j] = Bs[k][tx * 8 + j];
            #pragma unroll
            for (int i = 0; i < 8; i++)
                #pragma unroll
                for (int j = 0; j < 8; j++)
                    acc[i][j] = fmaf(a[i], b[j], acc[i][j]);
        }
        __syncthreads();
    }

    #pragma unroll
    for (int i = 0; i < 8; i++) {
        int row = bm + ty * 8 + i;
        size_t o = (size_t)row * FDIM + bn + tx * 8;
        #pragma unroll
        for (int j = 0; j < 8; j++) {
            float v = acc[i][j];
            if (row == bn + tx * 8 + j) v += RIDGE;
            g_A[o + j] = v;
        }
    }
}

// ---------------------------------------------------------------------------
// Tensor-core GEMM (3xTF32, on-the-fly hi/lo split):  g_Ap = p * A
//   p: [BATCH, FDIM] fp32;  A: [FDIM, FDIM] fp32 symmetric (B rows = A rows)
// CTA: 128 thr = 4 warps (2M x 2N), warp tile 64x64 (mt=4, nt=8).
// CTA tile 128x128, KC=32, cp.async double-buffered fp32 smem.
// Smem rows padded to 36 floats -> fragment LDS bank-conflict-free.
// ---------------------------------------------------------------------------
__global__ __launch_bounds__(128, 2) void sgemm_tc() {
    extern __shared__ __align__(16) float ds[];

    const int tid    = threadIdx.x;
    const int lane   = tid & 31;
    const int wid    = tid >> 5;
    const int warp_m = wid & 1;          // 0..1 -> 64-row half
    const int warp_n = wid >> 1;         // 0..1 -> 64-col half
    const int bm     = blockIdx.y * TILE_M;
    const int bn     = blockIdx.x * TILE_N;

    const uint32_t dsb = smem_u32(ds);

    // loader: thread t owns row t of both tiles (32 floats = 8 x 16B)
    const float* srcA = g_p + (size_t)(bm + tid) * FDIM;
    const float* srcB = g_A + (size_t)(bn + tid) * FDIM;
    const uint32_t srow = (uint32_t)tid * (ROW_STRIDE * 4);    // bytes

    float acc[4][8][4];
    #pragma unroll
    for (int mt = 0; mt < 4; mt++)
        #pragma unroll
        for (int nt = 0; nt < 8; nt++)
            #pragma unroll
            for (int k = 0; k < 4; k++) acc[mt][nt][k] = 0.f;

    auto stage = [&](int k0, int buf) {
        const uint32_t base = dsb + (uint32_t)buf * (BUFFLOATS * 4);
        #pragma unroll
        for (int c = 0; c < 8; c++) {
            cp_async16(base + srow + c * 16, srcA + k0 + c * 4);
            cp_async16(base + (TILEFLOATS * 4) + srow + c * 16, srcB + k0 + c * 4);
        }
        CP_COMMIT();
    };

    stage(0, 0);

    const int lr = lane >> 2;          // 0..7  fragment row within 8
    const int lc = lane & 3;           // 0..3  fragment k within 4

    #pragma unroll 1
    for (int i = 0; i < NCHUNK; i++) {
        const int buf = i & 1;

        __syncthreads();                    // prev compute done; buf^1 free
        if (i + 1 < NCHUNK) {
            stage((i + 1) * KC, buf ^ 1);
            CP_WAIT(1);                     // chunk i resident
        } else {
            CP_WAIT(0);
        }
        __syncthreads();                    // chunk i visible to all

        const float* sA = ds + (size_t)buf * BUFFLOATS;
        const float* sB = sA + TILEFLOATS;

        #pragma unroll
        for (int kst = 0; kst < KC / 8; kst++) {
            const int kb = kst * 8 + lc;

            // A fragments: 4 scalar LDS per mt, split to hi/lo in regs
            uint32_t aH[4][4], aL[4][4];
            #pragma unroll
            for (int mt = 0; mt < 4; mt++) {
                const int r0 = warp_m * 64 + mt * 16 + lr;
                const float v0 = sA[r0 * ROW_STRIDE + kb];
                const float v1 = sA[(r0 + 8) * ROW_STRIDE + kb];
                const float v2 = sA[r0 * ROW_STRIDE + kb + 4];
                const float v3 = sA[(r0 + 8) * ROW_STRIDE + kb + 4];
                const float h0 = tf32_hi(v0), h1 = tf32_hi(v1);
                const float h2 = tf32_hi(v2), h3 = tf32_hi(v3);
                aH[mt][0] = __float_as_uint(h0);
                aH[mt][1] = __float_as_uint(h1);
                aH[mt][2] = __float_as_uint(h2);
                aH[mt][3] = __float_as_uint(h3);
                aL[mt][0] = __float_as_uint(v0 - h0);
                aL[mt][1] = __float_as_uint(v1 - h1);
                aL[mt][2] = __float_as_uint(v2 - h2);
                aL[mt][3] = __float_as_uint(v3 - h3);
            }

            #pragma unroll
            for (int nt = 0; nt < 8; nt++) {
                const int nr = warp_n * 64 + nt * 8 + lr;
                const float w0 = sB[nr * ROW_STRIDE + kb];
                const float w1 = sB[nr * ROW_STRIDE + kb + 4];
                const float g0 = tf32_hi(w0), g1 = tf32_hi(w1);
                const uint32_t bH0 = __float_as_uint(g0);
                const uint32_t bH1 = __float_as_uint(g1);
                const uint32_t bL0 = __float_as_uint(w0 - g0);
                const uint32_t bL1 = __float_as_uint(w1 - g1);
                #pragma unroll
                for (int mt = 0; mt < 4; mt++) {
                    mma_tf32(acc[mt][nt], aH[mt], bH0, bH1);   // hi*hi
                    mma_tf32(acc[mt][nt], aH[mt], bL0, bL1);   // hi*lo
                    mma_tf32(acc[mt][nt], aL[mt], bH0, bH1);   // lo*hi
                }
            }
        }
    }

    // epilogue: m16n8 c-fragment -> float2 stores
    #pragma unroll
    for (int mt = 0; mt < 4; mt++) {
        const int row0 = bm + warp_m * 64 + mt * 16 + lr;
        #pragma unroll
        for (int nt = 0; nt < 8; nt++) {
            const int col = bn + warp_n * 64 + nt * 8 + 2 * lc;
            float* o0 = g_Ap + (size_t)row0 * FDIM + col;
            float* o1 = g_Ap + (size_t)(row0 + 8) * FDIM + col;
            *(float2*)o0 = make_float2(acc[mt][nt][0], acc[mt][nt][1]);
            *(float2*)o1 = make_float2(acc[mt][nt][2], acc[mt][nt][3]);
        }
    }
}

// ---------------------------------------------------------------------------
// Init: x = 0, r = b, p = b, rs = ||b||^2   (one 256-thread block per row)
// ---------------------------------------------------------------------------
__global__ __launch_bounds__(256) void cg_init(const float* __restrict__ b,
                                               float* __restrict__ x) {
    __shared__ float sh8[8];
    const size_t off = (size_t)blockIdx.x * FDIM;
    const int t = threadIdx.x;

    float4 v = ((const float4*)(b + off))[t];
    ((float4*)(x   + off))[t] = make_float4(0.f, 0.f, 0.f, 0.f);
    ((float4*)(g_r + off))[t] = v;
    ((float4*)(g_p + off))[t] = v;

    float s = v.x * v.x + v.y * v.y + v.z * v.z + v.w * v.w;
    s = block_reduce_sum_256(s, sh8);
    if (t == 0) g_rs[blockIdx.x] = s;
}

// ---------------------------------------------------------------------------
// Fused per-row CG vector step:
//   pAp; alpha; x += alpha p; r -= alpha Ap; rs_new; beta; p = r + beta p
// ---------------------------------------------------------------------------
__global__ __launch_bounds__(256) void cg_update(float* __restrict__ x) {
    __shared__ float sh8[8];
    const size_t off = (size_t)blockIdx.x * FDIM;
    const int t = threadIdx.x;

    float4 pv  = ((const float4*)(g_p  + off))[t];
    float4 apv = ((const float4*)(g_Ap + off))[t];

    float d = pv.x * apv.x + pv.y * apv.y + pv.z * apv.z + pv.w * apv.w;
    float pAp = block_reduce_sum_256(d, sh8);

    const float rs_old = g_rs[blockIdx.x];
    const float alpha  = rs_old / (pAp + EPS_CG);

    float4 xv = ((const float4*)(x   + off))[t];
    float4 rv = ((const float4*)(g_r + off))[t];

    xv.x = fmaf(alpha, pv.x, xv.x);   xv.y = fmaf(alpha, pv.y, xv.y);
    xv.z = fmaf(alpha, pv.z, xv.z);   xv.w = fmaf(alpha, pv.w, xv.w);
    rv.x = fmaf(-alpha, apv.x, rv.x); rv.y = fmaf(-alpha, apv.y, rv.y);
    rv.z = fmaf(-alpha, apv.z, rv.z); rv.w = fmaf(-alpha, apv.w, rv.w);

    ((float4*)(x + off))[t] = xv;

    float rn = rv.x * rv.x + rv.y * rv.y + rv.z * rv.z + rv.w * rv.w;
    float rs_new = block_reduce_sum_256(rn, sh8);

    const float beta = rs_new / (rs_old + EPS_CG);

    float4 pn;
    pn.x = fmaf(beta, pv.x, rv.x);  pn.y = fmaf(beta, pv.y, rv.y);
    pn.z = fmaf(beta, pv.z, rv.z);  pn.w = fmaf(beta, pv.w, rv.w);

    ((float4*)(g_r + off))[t] = rv;
    ((float4*)(g_p + off))[t] = pn;
    if (t == 0) g_rs[blockIdx.x] = rs_new;
}

// ---------------------------------------------------------------------------
// kernel_launch
//   d_in: b [16384x1024] f32, weight [1024x1024] f32 (order auto-detected)
//   d_out: solution [16384x1024] f32
// ---------------------------------------------------------------------------
extern "C" void kernel_launch(void* const* d_in, const int* in_sizes, int n_in,
                              void* d_out, int out_size) {
    (void)n_in; (void)out_size;

    const float* b;
    const float* W;
    if (in_sizes[0] == FDIM * FDIM) {
        W = (const float*)d_in[0];
        b = (const float*)d_in[1];
    } else {
        b = (const float*)d_in[0];
        W = (const float*)d_in[1];
    }
    float* x = (float*)d_out;

    cudaFuncSetAttribute(sgemm_tc, cudaFuncAttributeMaxDynamicSharedMemorySize,
                         SMEM_DYN);

    // A = W^T W + ridge I
    gemm_ata<<<dim3(FDIM / 128, FDIM / 128), 256>>>(W);

    // x=0, r=p=b, rs=||b||^2
    cg_init<<<BATCH, 256>>>(b, x);

    for (int it = 0; it < N_ITER; ++it) {
        sgemm_tc<<<dim3(FDIM / TILE_N, BATCH / TILE_M), 128, SMEM_DYN>>>();
        cg_update<<<BATCH, 256>>>(x);
    }
}